// round 8
// baseline (speedup 1.0000x reference)
#include <cuda_runtime.h>

// BidPrefix: per row of 302 floats = [rates[0..299], market_price, bid]
//   cp1[j] = prod(rates[0:j]),  cp1[0] = 1
//   out[row]          = cp1[bid]                     (survival_rate)
//   out[BATCH + row]  = cp1[mp] - cp1[mp+1]          (rate_last)
//
// Warp-per-row, single-pass: lane l owns elements [10l, 10l+10) (lanes 30,31
// contribute scan-neutral 1.0). Five predicated float2 streaming loads read
// only rates[0:lim), lim = max(bid, mp+1). One 5-step multiplicative warp
// shfl-scan; ~7 SHFL/row total. DRAM-bound by design (~400MB read / 4MB write).

static constexpr int SEQ_LEN    = 300;
static constexpr int ROW_STRIDE = SEQ_LEN + 2;   // 302
static constexpr int EPL        = 10;            // elements per lane

__global__ __launch_bounds__(256) void bidprefix_kernel(
    const float* __restrict__ in, float* __restrict__ out, int batch)
{
    const int gwarp = (blockIdx.x * blockDim.x + threadIdx.x) >> 5;
    if (gwarp >= batch) return;
    const int lane = threadIdx.x & 31;
    const float* __restrict__ row = in + (long long)gwarp * ROW_STRIDE;

    // mp & bid share one aligned 8B word (row stride 1208B keeps every row
    // base 8B-aligned); one LDG.64, warp-wide broadcast from a single sector.
    const float2 tail = __ldg((const float2*)(row + SEQ_LEN));
    const int mp  = (int)tail.x;
    const int bid = (int)tail.y;

    const int t0 = bid;            // cp1[bid]
    const int t1 = mp;             // cp1[mp]
    const int t2 = mp + 1;         // cp1[mp+1]  (>= 1)
    const int lim = max(t0, t2);   // need elements [0, lim), 1 <= lim <= 300

    const int e = lane * EPL;      // this lane's first element

    // 5 predicated float2 streaming loads; out-of-range elements become 1.0
    // (multiplicatively neutral). DRAM sectors past lim are never requested.
    float r[EPL];
    #pragma unroll
    for (int i = 0; i < EPL / 2; ++i) {
        const int e2 = e + 2 * i;
        float2 v = make_float2(1.f, 1.f);
        if (e2 < lim) v = __ldcs((const float2*)(row + e2));
        r[2 * i]     = v.x;
        r[2 * i + 1] = (e2 + 1 < lim) ? v.y : 1.f;
    }

    // local inclusive prefixes q[k] = prod(r[0..k]) (constant-indexed after
    // unroll -> register-resident)
    float q[EPL];
    q[0] = r[0];
    #pragma unroll
    for (int k = 1; k < EPL; ++k) q[k] = q[k - 1] * r[k];

    // multiplicative inclusive warp scan of per-lane totals (5 SHFL.UP)
    float incl = q[EPL - 1];
    #pragma unroll
    for (int off = 1; off < 32; off <<= 1) {
        const float v = __shfl_up_sync(0xffffffffu, incl, off);
        if (lane >= off) incl *= v;
    }
    const float excl = __shfl_up_sync(0xffffffffu, incl, 1);
    const float pre  = (lane == 0) ? 1.f : excl;   // prod of elements [0, e)

    // ownership: target t>0 has last element j = t-1; the lane holding j
    // computes cp1[t] = pre * q[j-e]. t=0 -> j=-1 matches no lane; the
    // default 1.0 on every lane then yields cp1[0] = 1.
    const int j0 = t0 - 1, j1 = t1 - 1, j2 = t2 - 1;
    float cand0 = 1.f, cand1 = 1.f, cand2 = 1.f;
    #pragma unroll
    for (int k = 0; k < EPL; ++k) {
        const float cp = pre * q[k];               // cp1[e+k+1]
        if (j0 == e + k) cand0 = cp;
        if (j1 == e + k) cand1 = cp;
        if (j2 == e + k) cand2 = cp;
    }

    // Owner lanes. C++ trunc division sends j = -1 to lane 0, where the
    // default cand = 1.0 = cp1[0] lives, so t = 0 needs no special case.
    // min() clamp is free and guards any out-of-spec index against UB shfl.
    const int ol0 = min(j0 / EPL, 31);
    const int ol1 = min(j1 / EPL, 31);
    const int ol2 = min(j2 / EPL, 31);

    // survival_rate: owner lane writes directly (no broadcast needed)
    if (lane == ol0) out[gwarp] = cand0;

    // rate_last needs both values on one lane -> two broadcasts
    const float v1 = __shfl_sync(0xffffffffu, cand1, ol1);
    const float v2 = __shfl_sync(0xffffffffu, cand2, ol2);
    if (lane == 0) out[batch + gwarp] = v1 - v2;   // cp1[mp] - cp1[mp+1]
}

extern "C" void kernel_launch(void* const* d_in, const int* in_sizes, int n_in,
                              void* d_out, int out_size) {
    const float* in = (const float*)d_in[0];
    float* out = (float*)d_out;
    // out = [survival(B); rate_last(B)] -> B = out_size/2 (== in_sizes[0]/302)
    const int batch = out_size / 2;                   // 500000

    const int threads = 256;                          // 8 warps = 8 rows / block
    const int blocks  = (batch * 32 + threads - 1) / threads;
    bidprefix_kernel<<<blocks, threads>>>(in, out, batch);
}

// round 9
// speedup vs baseline: 1.2666x; 1.2666x over previous
#include <cuda_runtime.h>

// BidPrefix: per row of 302 floats = [rates[0..299], market_price, bid]
//   cp1[j] = prod(rates[0:j]),  cp1[0] = 1
//   out[row]          = cp1[bid]                      (survival_rate)
//   out[BATCH + row]  = cp1[mp]*(1 - rates[mp])       (== cp1[mp]-cp1[mp+1])
//
// Issue-bound per R8 ncu (alu 63.7%, issue 64.2%, DRAM 49.9%) -> this round
// minimizes warp-instructions: t2 folded into t1 via (1-rates[mp]); 9-SEL
// binary tree replaces ==-match selection loops; owner lanes write outputs
// directly (no broadcast shfls); odd-element load fixups removed (provably
// never selected).

static constexpr int SEQ_LEN    = 300;
static constexpr int ROW_STRIDE = SEQ_LEN + 2;   // 302
static constexpr int EPL        = 10;            // elements per lane

// Select q[K] for K in [0,9] with a 9-FSEL tree (garbage for K outside range).
__device__ __forceinline__ float select10(const float q[EPL], int K) {
    const bool b0 = (K & 1) != 0;
    const bool b1 = (K & 2) != 0;
    const bool b2 = (K & 4) != 0;
    const bool b3 = (K & 8) != 0;
    const float m0 = b0 ? q[1] : q[0];
    const float m1 = b0 ? q[3] : q[2];
    const float m2 = b0 ? q[5] : q[4];
    const float m3 = b0 ? q[7] : q[6];
    const float m4 = b0 ? q[9] : q[8];
    const float n0 = b1 ? m1 : m0;
    const float n1 = b1 ? m3 : m2;
    const float p0 = b2 ? n1 : n0;
    return b3 ? m4 : p0;
}

__global__ __launch_bounds__(256) void bidprefix_kernel(
    const float* __restrict__ in, float* __restrict__ out, int batch)
{
    const int gwarp = (blockIdx.x * blockDim.x + threadIdx.x) >> 5;
    if (gwarp >= batch) return;
    const int lane = threadIdx.x & 31;
    const float* __restrict__ row = in + (long long)gwarp * ROW_STRIDE;

    // mp & bid share one aligned 8B word; warp-broadcast load
    const float2 tail = __ldg((const float2*)(row + SEQ_LEN));
    const int mp  = (int)tail.x;       // 0..299
    const int bid = (int)tail.y;       // 0..300

    // rates[mp]: uniform address -> broadcast, sector usually shared with scan
    const float rmp = __ldg(row + mp);

    // Targets: t0 = bid, t1 = mp. Needed elements: [0, lim).
    const int lim = max(bid, mp);      // 0..300 (lim==0 -> no loads, all fine)

    const int e = lane * EPL;          // this lane's first element

    // 5 predicated float2 streaming loads. A pair loads iff its first element
    // is in range; a possible over-read element at index lim lands at local
    // position m = lim-e, but the largest q index ever selected on this lane
    // is lim-1-e = m-1, so no fixup is needed. Elements in unloaded pairs
    // stay 1.0 (scan-neutral). All junk is finite (real data in [0.9,1)).
    float r[EPL];
    #pragma unroll
    for (int i = 0; i < EPL / 2; ++i) {
        float2 v = make_float2(1.f, 1.f);
        if (e + 2 * i < lim) v = __ldcs((const float2*)(row + e + 2 * i));
        r[2 * i]     = v.x;
        r[2 * i + 1] = v.y;
    }

    // local inclusive prefixes q[k] = prod(r[0..k])
    float q[EPL];
    q[0] = r[0];
    #pragma unroll
    for (int k = 1; k < EPL; ++k) q[k] = q[k - 1] * r[k];

    // multiplicative inclusive warp scan of per-lane totals (5 SHFL.UP)
    float incl = q[EPL - 1];
    #pragma unroll
    for (int off = 1; off < 32; off <<= 1) {
        const float v = __shfl_up_sync(0xffffffffu, incl, off);
        if (lane >= off) incl *= v;
    }
    const float excl = __shfl_up_sync(0xffffffffu, incl, 1);
    const float pre  = (lane == 0) ? 1.f : excl;   // prod of elements [0, e)

    // cp1[t] = pre * q[t-1-e] on owner lane (t-1)/10. t==0 overrides to 1.0.
    const int K0 = bid - 1 - e;
    const int K1 = mp  - 1 - e;
    const float v0 = (bid == 0) ? 1.f : pre * select10(q, K0);
    const float v1 = (mp  == 0) ? 1.f : pre * select10(q, K1);

    // Owner lanes (C trunc: -1/10 = 0, where the t==0 override lives).
    const int ol0 = (bid - 1) / EPL;   // <= 29
    const int ol1 = (mp  - 1) / EPL;   // <= 29

    if (lane == ol0) out[gwarp] = v0;                        // survival_rate
    if (lane == ol1) out[batch + gwarp] = v1 * (1.f - rmp);  // rate_last
}

extern "C" void kernel_launch(void* const* d_in, const int* in_sizes, int n_in,
                              void* d_out, int out_size) {
    const float* in = (const float*)d_in[0];
    float* out = (float*)d_out;
    const int batch = out_size / 2;                   // 500000

    const int threads = 256;                          // 8 warps = 8 rows / block
    const int blocks  = (batch * 32 + threads - 1) / threads;
    bidprefix_kernel<<<blocks, threads>>>(in, out, batch);
}

// round 11
// speedup vs baseline: 1.4322x; 1.1307x over previous
#include <cuda_runtime.h>

// BidPrefix: per row of 302 floats = [rates[0..299], market_price, bid]
//   cp1[j] = prod(rates[0:j]),  cp1[0] = 1
//   out[row]          = cp1[bid]                      (survival_rate)
//   out[BATCH + row]  = cp1[mp]*(1 - rates[mp])       (== cp1[mp]-cp1[mp+1])
//
// R9 ncu: DRAM 60.5%, issue 56%, occ 77% -> latency-bound, DRAM idles during
// each warp's serial scan tail. This round: 2 rows per warp. Both rows' loads
// issue up front (2x MLP), the two independent shfl-scan chains interleave
// (mutual latency hiding), prologue/scan predicates amortized. Owner-lane
// test via unsigned-range check (no division).

static constexpr int SEQ_LEN    = 300;
static constexpr int ROW_STRIDE = SEQ_LEN + 2;   // 302
static constexpr int EPL        = 10;            // elements per lane

// Select q[K] for K in [0,9] with a SEL tree (garbage outside range is fine).
__device__ __forceinline__ float select10(const float q[EPL], int K) {
    const bool b0 = (K & 1) != 0;
    const bool b1 = (K & 2) != 0;
    const bool b2 = (K & 4) != 0;
    const bool b3 = (K & 8) != 0;
    const float m0 = b0 ? q[1] : q[0];
    const float m1 = b0 ? q[3] : q[2];
    const float m2 = b0 ? q[5] : q[4];
    const float m3 = b0 ? q[7] : q[6];
    const float m4 = b0 ? q[9] : q[8];
    const float n0 = b1 ? m1 : m0;
    const float n1 = b1 ? m3 : m2;
    const float p0 = b2 ? n1 : n0;
    return b3 ? m4 : p0;
}

__global__ __launch_bounds__(256) void bidprefix_kernel(
    const float* __restrict__ in, float* __restrict__ out, int batch)
{
    const int gw   = (blockIdx.x * blockDim.x + threadIdx.x) >> 5;
    const int lane = threadIdx.x & 31;
    const int rA = 2 * gw;
    const int rB = rA + 1;
    if (rA >= batch) return;
    const bool hasB = (rB < batch);

    const float* __restrict__ rowA = in + (long long)rA * ROW_STRIDE;
    const float* __restrict__ rowB = hasB ? rowA + ROW_STRIDE : rowA;

    // tails: mp & bid share one aligned 8B word per row
    const float2 tA = __ldg((const float2*)(rowA + SEQ_LEN));
    const float2 tB = __ldg((const float2*)(rowB + SEQ_LEN));
    const int mpA = (int)tA.x, bidA = (int)tA.y;
    const int mpB = (int)tB.x, bidB = (int)tB.y;

    const float rmpA = __ldg(rowA + mpA);   // uniform-address broadcast
    const float rmpB = __ldg(rowB + mpB);

    const int limA = max(bidA, mpA);        // need [0, limA)
    const int limB = hasB ? max(bidB, mpB) : 0;

    const int e = lane * EPL;

    // ---- load phase: both rows' predicated float2 streams in flight ----
    float a[EPL], b[EPL];
    #pragma unroll
    for (int i = 0; i < EPL / 2; ++i) {
        float2 v = make_float2(1.f, 1.f);
        float2 w = make_float2(1.f, 1.f);
        if (e + 2 * i < limA) v = __ldcs((const float2*)(rowA + e + 2 * i));
        if (e + 2 * i < limB) w = __ldcs((const float2*)(rowB + e + 2 * i));
        a[2 * i] = v.x; a[2 * i + 1] = v.y;
        b[2 * i] = w.x; b[2 * i + 1] = w.y;
        // A possible over-read element at index lim lands at local pos
        // lim-e, but the largest q index selected on this lane is lim-1-e,
        // so no fixup needed; unloaded pairs stay scan-neutral 1.0.
    }

    // ---- local inclusive prefixes, in place (both rows interleaved) ----
    #pragma unroll
    for (int k = 1; k < EPL; ++k) { a[k] *= a[k - 1]; b[k] *= b[k - 1]; }

    // ---- warp scans, chains interleaved for mutual latency hiding ----
    float iA = a[EPL - 1], iB = b[EPL - 1];
    #pragma unroll
    for (int off = 1; off < 32; off <<= 1) {
        const float vA = __shfl_up_sync(0xffffffffu, iA, off);
        const float vB = __shfl_up_sync(0xffffffffu, iB, off);
        if (lane >= off) { iA *= vA; iB *= vB; }
    }
    const float exA = __shfl_up_sync(0xffffffffu, iA, 1);
    const float exB = __shfl_up_sync(0xffffffffu, iB, 1);
    const float preA = lane ? exA : 1.f;    // prod of elements [0, e)
    const float preB = lane ? exB : 1.f;

    // ---- selection + direct owner-lane stores ----
    // cp1[t] = pre * q[t-1-e] on the lane where K = t-1-e is in [0,10).
    // t == 0: value is 1.0, written by lane 0.
    {
        const int K0 = bidA - 1 - e, K1 = mpA - 1 - e;
        const float v0 = bidA ? preA * select10(a, K0) : 1.f;
        const float v1 = mpA  ? preA * select10(a, K1) : 1.f;
        const bool w0 = ((unsigned)K0 < 10u) || (bidA == 0 && lane == 0);
        const bool w1 = ((unsigned)K1 < 10u) || (mpA  == 0 && lane == 0);
        if (w0) out[rA] = v0;                            // survival_rate
        if (w1) out[batch + rA] = v1 * (1.f - rmpA);     // rate_last
    }
    if (hasB) {
        const int K0 = bidB - 1 - e, K1 = mpB - 1 - e;
        const float v0 = bidB ? preB * select10(b, K0) : 1.f;
        const float v1 = mpB  ? preB * select10(b, K1) : 1.f;
        const bool w0 = ((unsigned)K0 < 10u) || (bidB == 0 && lane == 0);
        const bool w1 = ((unsigned)K1 < 10u) || (mpB  == 0 && lane == 0);
        if (w0) out[rB] = v0;
        if (w1) out[batch + rB] = v1 * (1.f - rmpB);
    }
}

extern "C" void kernel_launch(void* const* d_in, const int* in_sizes, int n_in,
                              void* d_out, int out_size) {
    const float* in = (const float*)d_in[0];
    float* out = (float*)d_out;
    const int batch = out_size / 2;                     // 500000

    const int nwarps  = (batch + 1) / 2;                // 2 rows per warp
    const int threads = 256;                            // 8 warps per block
    const int blocks  = (nwarps * 32 + threads - 1) / threads;
    bidprefix_kernel<<<blocks, threads>>>(in, out, batch);
}